// round 15
// baseline (speedup 1.0000x reference)
#include <cuda_runtime.h>
#include <cuda_bf16.h>
#include <math.h>
#include <stdint.h>

// GaussianScorer sm_103a — SINGLE kernel, no prep launch, no global scratch.
// 512 threads: thr 0-255 produce A (emb fp32 -> e2 -> bf16 STS),
//              thr 256-511 produce B (means fp32 * inv_var -> m2 -> bf16 STS),
// all 16 warps consume (ldmatrix + mma.sync bf16, 32x32 warp tiles).
// out[m,l] = logc - 0.5*e2[m] - 0.5*m2[l] + cross[m,l]
// Shapes: M=16384, L=128, K=512.  BM=128, BK=32, 2-stage ring, grid=128.

#define GS_M 16384
#define GS_K 512
#define GS_L 128
#define BM   128
#define BKT  32
#define NITER (GS_K / BKT)   // 16
#define NTHREADS 512

#define IV_OFF   0           // 512 f32 inv_var
#define LOGC_OFF 2048        // 1 f32
#define RED_OFF  2064        // 4 f32
#define E2_OFF   2304        // 2*128 f32
#define M2_OFF   3328        // 2*128 f32
#define A_OFF    8192        // 2 stages * 8192 (128 rows * 64B)
#define B_OFF    24576       // 2 stages * 8192
#define SMEM_TOTAL 40960

static __device__ __forceinline__ uint32_t smem_u32(const void* p) {
    uint32_t a;
    asm("{ .reg .u64 t; cvta.to.shared.u64 t, %1; cvt.u32.u64 %0, t; }" : "=r"(a) : "l"(p));
    return a;
}

#define LDSM_X4(r, addr)                                                        \
    asm volatile("ldmatrix.sync.aligned.m8n8.x4.shared.b16 {%0,%1,%2,%3}, [%4];" \
        : "=r"((r)[0]), "=r"((r)[1]), "=r"((r)[2]), "=r"((r)[3]) : "r"(addr))

#define MMA_BF16(d, a, b0, b1)                                                  \
    asm volatile("mma.sync.aligned.m16n8k16.row.col.f32.bf16.bf16.f32 "         \
        "{%0,%1,%2,%3}, {%4,%5,%6,%7}, {%8,%9}, {%0,%1,%2,%3};"                 \
        : "+f"((d)[0]), "+f"((d)[1]), "+f"((d)[2]), "+f"((d)[3])                \
        : "r"((a)[0]), "r"((a)[1]), "r"((a)[2]), "r"((a)[3]), "r"(b0), "r"(b1))

// 64B rows, 4 x 16B chunks, chunk ^= (row>>1)&3   (proven in R5 best kernel)
#define SWZ(row, chunk) ((uint32_t)((row) * 64 + (((chunk) ^ (((row) >> 1) & 3)) << 4)))

__global__ __launch_bounds__(NTHREADS, 1)
void gs_main(const float* __restrict__ emb, const float* __restrict__ means,
             const float* __restrict__ var, float* __restrict__ out) {
    extern __shared__ __align__(1024) char smem[];
    const uint32_t sb = smem_u32(smem);
    const int tid = threadIdx.x;
    const int m0 = blockIdx.x * BM;

    // ---- tables: inv_var + logc partials ----
    float lv = 0.0f;
    if (tid < 128) {
        float4 v4 = *(const float4*)(var + tid * 4);
        *(float4*)(smem + IV_OFF + tid * 16) =
            make_float4(1.0f / v4.x, 1.0f / v4.y, 1.0f / v4.z, 1.0f / v4.w);
        lv = __logf(v4.x) + __logf(v4.y) + __logf(v4.z) + __logf(v4.w);
    }
    #pragma unroll
    for (int o = 16; o > 0; o >>= 1) lv += __shfl_xor_sync(0xffffffffu, lv, o);
    if (tid < 128 && (tid & 31) == 0) ((float*)(smem + RED_OFF))[tid >> 5] = lv;
    __syncthreads();                  // IV + RED ready
    if (tid == 0) {
        const float* rd = (const float*)(smem + RED_OFF);
        const float FACTOR = -256.0f * 1.8378770664093453f;   // -E/2 * ln(2*pi)
        ((float*)(smem + LOGC_OFF))[0] = FACTOR - 0.5f * (rd[0] + rd[1] + rd[2] + rd[3]);
    }

    // ---- producer role ----
    const int isA = (tid < 256);
    const int p = isA ? tid : tid - 256;
    const int prow = p >> 1;          // 0..127 (A: M-row; B: L-row)
    const int hh = p & 1;             // 16-k half within BK=32
    const uint32_t st0 = SWZ(prow, hh * 2);
    const uint32_t st1 = SWZ(prow, hh * 2 + 1);
    const uint32_t pbase = isA ? (uint32_t)A_OFF : (uint32_t)B_OFF;
    const float* src = (isA ? emb + (size_t)(m0 + prow) * GS_K
                            : means + (size_t)prow * GS_K) + hh * 16;
    const float* ivp = (const float*)(smem + IV_OFF);
    float accp = 0.0f;                // e2 (A role) or m2 (B role) partial

    #define LDG16(rr, kt) do {                                                  \
        rr[0] = *(const float4*)(src + (kt));                                   \
        rr[1] = *(const float4*)(src + (kt) + 4);                               \
        rr[2] = *(const float4*)(src + (kt) + 8);                               \
        rr[3] = *(const float4*)(src + (kt) + 12);                              \
    } while (0)

    // t = x*iv; acc += x*t; store bf16(A ? x : t)
    #define PROD(s, rr, kt) do {                                                \
        const float* _iv = ivp + (kt) + hh * 16;                                \
        uint32_t _cv[8];                                                        \
        _Pragma("unroll")                                                       \
        for (int _q = 0; _q < 4; _q++) {                                        \
            float4 _x = rr[_q];                                                 \
            float4 _v = *(const float4*)(_iv + _q * 4);                         \
            float4 _t = make_float4(_x.x * _v.x, _x.y * _v.y,                   \
                                    _x.z * _v.z, _x.w * _v.w);                  \
            accp = fmaf(_x.x, _t.x, accp);                                      \
            accp = fmaf(_x.y, _t.y, accp);                                      \
            accp = fmaf(_x.z, _t.z, accp);                                      \
            accp = fmaf(_x.w, _t.w, accp);                                      \
            float4 _c = isA ? _x : _t;                                          \
            __nv_bfloat162 _b0 = __floats2bfloat162_rn(_c.x, _c.y);             \
            __nv_bfloat162 _b1 = __floats2bfloat162_rn(_c.z, _c.w);             \
            _cv[_q * 2]     = *(uint32_t*)&_b0;                                 \
            _cv[_q * 2 + 1] = *(uint32_t*)&_b1;                                 \
        }                                                                       \
        const uint32_t _ao = pbase + (s) * 8192;                                \
        *(uint4*)(smem + _ao + st0) = make_uint4(_cv[0], _cv[1], _cv[2], _cv[3]);\
        *(uint4*)(smem + _ao + st1) = make_uint4(_cv[4], _cv[5], _cv[6], _cv[7]);\
    } while (0)

    float4 rr0[4], rr1[4];

    // ---- prologue ----
    LDG16(rr0, 0);
    PROD(0, rr0, 0);                  // stage 0 (IV ready after the sync above)
    LDG16(rr1, BKT);                  // regs for stage 1

    // ---- consumer constants (R5-proven 4x4 warp grid, 32x32 tiles) ----
    const int lane = tid & 31;
    const int g = lane >> 2;
    const int tig = lane & 3;
    const int wid = tid >> 5;
    const int wm = wid >> 2;          // 0..3
    const int wn = wid & 3;           // 0..3
    const int mm = lane >> 3;
    const int mrow = lane & 7;
    const int rowA0 = wm * 32 + (mm & 1) * 8 + mrow;
    const int rowB0 = wn * 32 + (mm >> 1) * 8 + mrow;
    const int cA = mm >> 1;
    const int cB = mm & 1;

    float acc[2][4][4];
    #pragma unroll
    for (int mt = 0; mt < 2; mt++)
        #pragma unroll
        for (int nt = 0; nt < 4; nt++)
            #pragma unroll
            for (int j = 0; j < 4; j++) acc[mt][nt][j] = 0.0f;

    #pragma unroll
    for (int it = 0; it < NITER; ++it) {
        __syncthreads();              // stage it visible to all

        // deep LDG prefetch (consumed by PROD next iter)
        if (it + 2 < NITER) {
            if (it & 1) LDG16(rr1, (it + 2) * BKT);
            else        LDG16(rr0, (it + 2) * BKT);
        }

        const uint32_t As = sb + A_OFF + (it & 1) * 8192;
        const uint32_t Bs = sb + B_OFF + (it & 1) * 8192;

        #pragma unroll
        for (int ks = 0; ks < 2; ks++) {
            const int c0 = ks * 2;
            uint32_t af[2][4], bq[2][4];
            LDSM_X4(af[0], As + SWZ(rowA0,      c0 + cA));
            LDSM_X4(af[1], As + SWZ(rowA0 + 16, c0 + cA));
            LDSM_X4(bq[0], Bs + SWZ(rowB0,      c0 + cB));
            LDSM_X4(bq[1], Bs + SWZ(rowB0 + 16, c0 + cB));
            #pragma unroll
            for (int mt = 0; mt < 2; mt++) {
                MMA_BF16(acc[mt][0], af[mt], bq[0][0], bq[0][1]);
                MMA_BF16(acc[mt][1], af[mt], bq[0][2], bq[0][3]);
                MMA_BF16(acc[mt][2], af[mt], bq[1][0], bq[1][1]);
                MMA_BF16(acc[mt][3], af[mt], bq[1][2], bq[1][3]);
            }
        }

        // convert+store stage it+1 from regs loaded last iter
        if (it + 1 < NITER) {
            if (it & 1) { PROD((it + 1) & 1, rr0, (it + 1) * BKT); }
            else        { PROD((it + 1) & 1, rr1, (it + 1) * BKT); }
        }
    }

    // ---- publish e2/m2 partials ----
    if (isA) ((float*)(smem + E2_OFF))[hh * 128 + prow] = accp;
    else     ((float*)(smem + M2_OFF))[hh * 128 + prow] = accp;
    __syncthreads();

    const float* sE2 = (const float*)(smem + E2_OFF);
    const float* sM2 = (const float*)(smem + M2_OFF);
    const float logc = ((const float*)(smem + LOGC_OFF))[0];

    // ---- epilogue: out = cross - 0.5*e2[m] + (logc - 0.5*m2[l]) ----
    #pragma unroll
    for (int mt = 0; mt < 2; mt++) {
        const int r0 = wm * 32 + mt * 16 + g;
        const float rb0 = -0.5f * (sE2[r0] + sE2[128 + r0]);
        const float rb1 = -0.5f * (sE2[r0 + 8] + sE2[128 + r0 + 8]);
        float* orow0 = out + (size_t)(m0 + r0) * GS_L;
        float* orow1 = orow0 + 8 * GS_L;
        #pragma unroll
        for (int nt = 0; nt < 4; nt++) {
            const int col = wn * 32 + nt * 8 + tig * 2;
            const float mox = logc - 0.5f * (sM2[col] + sM2[128 + col]);
            const float moy = logc - 0.5f * (sM2[col + 1] + sM2[128 + col + 1]);
            float2 o0, o1;
            o0.x = acc[mt][nt][0] + rb0 + mox;
            o0.y = acc[mt][nt][1] + rb0 + moy;
            o1.x = acc[mt][nt][2] + rb1 + mox;
            o1.y = acc[mt][nt][3] + rb1 + moy;
            *(float2*)(orow0 + col) = o0;
            *(float2*)(orow1 + col) = o1;
        }
    }
}

extern "C" void kernel_launch(void* const* d_in, const int* in_sizes, int n_in,
                              void* d_out, int out_size) {
    const float* emb   = (const float*)d_in[0];   // [8, 2048, 512] f32
    const float* means = (const float*)d_in[1];   // [128, 512] f32
    const float* var   = (const float*)d_in[2];   // [512] f32
    float* out = (float*)d_out;                   // [8, 2048, 128] f32
    (void)in_sizes; (void)n_in; (void)out_size;

    cudaFuncSetAttribute(gs_main, cudaFuncAttributeMaxDynamicSharedMemorySize, SMEM_TOTAL);
    gs_main<<<GS_M / BM, NTHREADS, SMEM_TOTAL>>>(emb, means, var, out);
}

// round 16
// speedup vs baseline: 1.0894x; 1.0894x over previous
#include <cuda_runtime.h>
#include <cuda_bf16.h>
#include <math.h>
#include <stdint.h>

// GaussianScorer sm_103a: bf16 mma.sync + ldmatrix + cp.async, k-split warps.
// BM=64, BK=32, 4-stage ring, 512 threads, grid=256.
// 16 warps = 2(k-half) x 2(m:32) x 4(n:32); each warp 4 LDSM + 8 MMA / iter.
// Epilogue: k-pair reduction through SMEM (stage buffers reused).
// out[m,l] = logc - 0.5*e2[m] - 0.5*m2[l] + cross[m,l]
// Shapes: M=16384, L=128, K=512.

#define GS_M 16384
#define GS_K 512
#define GS_L 128
#define BM   64
#define BKT  32
#define NITER (GS_K / BKT)   // 16
#define NSTG 4
#define NTHREADS 512

#define A_STAGE 4096                 // 64 rows * 64B (32 bf16)
#define B_STAGE 8192                 // 128 rows * 64B
#define IV_OFF   0                   // 512 f32 inv_var
#define MOFF_OFF 2048                // 128 f32: logc - 0.5*m2[l]
#define E2_OFF   2560                // 4*64 f32 partials
#define A_OFF    4096
#define B_OFF    (A_OFF + NSTG * A_STAGE)     // 20480
#define SMEM_TOTAL (B_OFF + NSTG * B_STAGE)   // 53248
// k-reduction area: reuses stage buffers (8 pairs * 4KB at A_OFF)

__device__ __nv_bfloat16 g_Bh[GS_L * GS_K];
__device__ float g_m2[GS_L];
__device__ float g_logc;

static __device__ __forceinline__ uint32_t smem_u32(const void* p) {
    uint32_t a;
    asm("{ .reg .u64 t; cvta.to.shared.u64 t, %1; cvt.u32.u64 %0, t; }" : "=r"(a) : "l"(p));
    return a;
}

#define CP_ASYNC16(dst, src) \
    asm volatile("cp.async.cg.shared.global [%0], [%1], 16;" :: "r"(dst), "l"(src) : "memory")
#define CP_COMMIT() asm volatile("cp.async.commit_group;" ::: "memory")
#define CP_WAIT2()  asm volatile("cp.async.wait_group 2;" ::: "memory")

#define LDSM_X4(r, addr)                                                        \
    asm volatile("ldmatrix.sync.aligned.m8n8.x4.shared.b16 {%0,%1,%2,%3}, [%4];" \
        : "=r"((r)[0]), "=r"((r)[1]), "=r"((r)[2]), "=r"((r)[3]) : "r"(addr))

#define MMA_BF16(d, a, b0, b1)                                                  \
    asm volatile("mma.sync.aligned.m16n8k16.row.col.f32.bf16.bf16.f32 "         \
        "{%0,%1,%2,%3}, {%4,%5,%6,%7}, {%8,%9}, {%0,%1,%2,%3};"                 \
        : "+f"((d)[0]), "+f"((d)[1]), "+f"((d)[2]), "+f"((d)[3])                \
        : "r"((a)[0]), "r"((a)[1]), "r"((a)[2]), "r"((a)[3]), "r"(b0), "r"(b1))

// 64B rows, 4 x 16B chunks, chunk ^= (row>>1)&3   (proven since R5)
#define SWZ(row, chunk) ((uint32_t)((row) * 64 + (((chunk) ^ (((row) >> 1) & 3)) << 4)))

// ---------------- prep: g_Bh = bf16(means*inv_var), g_m2, g_logc ----------------
__global__ void gs_prep(const float* __restrict__ means, const float* __restrict__ var) {
    __shared__ float red[4];
    const int l = blockIdx.x;
    const int t = threadIdx.x;        // 128 threads, 4 elems each
    const int i0 = t * 4;

    float4 v4 = *(const float4*)(var + i0);
    float4 m4 = *(const float4*)(means + (size_t)l * GS_K + i0);
    float4 b4 = make_float4(__fdividef(m4.x, v4.x), __fdividef(m4.y, v4.y),
                            __fdividef(m4.z, v4.z), __fdividef(m4.w, v4.w));

    __nv_bfloat162 p0 = __floats2bfloat162_rn(b4.x, b4.y);
    __nv_bfloat162 p1 = __floats2bfloat162_rn(b4.z, b4.w);
    *(uint2*)(g_Bh + (size_t)l * GS_K + i0) =
        make_uint2(*(uint32_t*)&p0, *(uint32_t*)&p1);

    float m2 = m4.x * b4.x + m4.y * b4.y + m4.z * b4.z + m4.w * b4.w;
    #pragma unroll
    for (int o = 16; o > 0; o >>= 1) m2 += __shfl_xor_sync(0xffffffffu, m2, o);
    if ((t & 31) == 0) red[t >> 5] = m2;
    __syncthreads();
    if (t == 0) g_m2[l] = red[0] + red[1] + red[2] + red[3];

    if (l == 0) {
        __syncthreads();
        float lg = __logf(v4.x) + __logf(v4.y) + __logf(v4.z) + __logf(v4.w);
        #pragma unroll
        for (int o = 16; o > 0; o >>= 1) lg += __shfl_xor_sync(0xffffffffu, lg, o);
        if ((t & 31) == 0) red[t >> 5] = lg;
        __syncthreads();
        if (t == 0) {
            const float FACTOR = -256.0f * 1.8378770664093453f;   // -E/2 * ln(2*pi)
            g_logc = FACTOR - 0.5f * (red[0] + red[1] + red[2] + red[3]);
        }
    }
}

// ---------------- main kernel ----------------
__global__ __launch_bounds__(NTHREADS, 1)
void gs_main(const float* __restrict__ emb, const float* __restrict__ var,
             float* __restrict__ out) {
    extern __shared__ __align__(1024) char smem[];
    const uint32_t sb = smem_u32(smem);
    const int tid = threadIdx.x;
    const int m0 = blockIdx.x * BM;

    // ---- tables ----
    if (tid < 128) {
        float4 v4 = *(const float4*)(var + tid * 4);
        *(float4*)(smem + IV_OFF + tid * 16) =
            make_float4(1.0f / v4.x, 1.0f / v4.y, 1.0f / v4.z, 1.0f / v4.w);
        ((float*)(smem + MOFF_OFF))[tid] = g_logc - 0.5f * g_m2[tid];
    }

    // ---- producer roles ----
    const int isA = (tid < 256);
    // A role (tid 0..255): (row 0..63, 8-k quarter)
    const int arow = (tid & 255) >> 2;
    const int aq = tid & 3;
    const uint32_t stsA = SWZ(arow, aq);
    const float* aSrc = emb + (size_t)(m0 + arow) * GS_K + aq * 8;
    // B role (tid 256..511): (row 0..127, 16-k half) -> 2 cp.async
    const int bp = tid & 255;
    const int brow = bp >> 1;
    const int bh = bp & 1;
    const uint32_t stB0 = SWZ(brow, bh * 2);
    const uint32_t stB1 = SWZ(brow, bh * 2 + 1);
    const __nv_bfloat16* bSrc = g_Bh + (size_t)brow * GS_K + bh * 16;

    const float* ivp = (const float*)(smem + IV_OFF);
    float e2p = 0.0f;

    #define LDG_A(rr, kt) do {                                                  \
        rr[0] = *(const float4*)(aSrc + (kt));                                  \
        rr[1] = *(const float4*)(aSrc + (kt) + 4);                              \
    } while (0)

    #define PROD(s, rr, kt) do {                                                \
        const float* _iv = ivp + (kt) + aq * 8;                                 \
        float4 _v0 = *(const float4*)(_iv);                                     \
        float4 _v1 = *(const float4*)(_iv + 4);                                 \
        e2p = fmaf(rr[0].x * rr[0].x, _v0.x, e2p);                              \
        e2p = fmaf(rr[0].y * rr[0].y, _v0.y, e2p);                              \
        e2p = fmaf(rr[0].z * rr[0].z, _v0.z, e2p);                              \
        e2p = fmaf(rr[0].w * rr[0].w, _v0.w, e2p);                              \
        e2p = fmaf(rr[1].x * rr[1].x, _v1.x, e2p);                              \
        e2p = fmaf(rr[1].y * rr[1].y, _v1.y, e2p);                              \
        e2p = fmaf(rr[1].z * rr[1].z, _v1.z, e2p);                              \
        e2p = fmaf(rr[1].w * rr[1].w, _v1.w, e2p);                              \
        __nv_bfloat162 _c0 = __floats2bfloat162_rn(rr[0].x, rr[0].y);           \
        __nv_bfloat162 _c1 = __floats2bfloat162_rn(rr[0].z, rr[0].w);           \
        __nv_bfloat162 _c2 = __floats2bfloat162_rn(rr[1].x, rr[1].y);           \
        __nv_bfloat162 _c3 = __floats2bfloat162_rn(rr[1].z, rr[1].w);           \
        *(uint4*)(smem + A_OFF + (s) * A_STAGE + stsA) =                        \
            make_uint4(*(uint32_t*)&_c0, *(uint32_t*)&_c1,                      \
                       *(uint32_t*)&_c2, *(uint32_t*)&_c3);                     \
    } while (0)

    #define CPB(s, kt) do {                                                    \
        const uint32_t _bb = sb + B_OFF + (s) * B_STAGE;                        \
        CP_ASYNC16(_bb + stB0, (const char*)(bSrc + (kt)));                     \
        CP_ASYNC16(_bb + stB1, (const char*)(bSrc + (kt) + 8));                 \
        CP_COMMIT();                                                            \
    } while (0)

    float4 rr0[2], rr1[2];

    // ---- prologue ----
    if (isA) LDG_A(rr0, 0);
    else { CPB(0, 0); CPB(1, BKT); CPB(2, 2 * BKT); }
    __syncthreads();                  // IV table ready
    if (isA) { PROD(0, rr0, 0); LDG_A(rr1, BKT); }

    // ---- consumer constants: 16 warps = kh(2) x wm(2) x wn(4), 32x32 tiles ----
    const int lane = tid & 31;
    const int g = lane >> 2;
    const int tig = lane & 3;
    const int wid = tid >> 5;
    const int kh = wid >> 3;          // k-half 0/1
    const int wm = (wid >> 2) & 1;    // 0..1 -> 32 rows
    const int wn = wid & 3;           // 0..3 -> 32 cols
    const int mm = lane >> 3;
    const int mrow = lane & 7;
    const int rowA0 = wm * 32 + (mm & 1) * 8 + mrow;
    const int rowB0 = wn * 32 + (mm >> 1) * 8 + mrow;
    const int ckA = kh * 2 + (mm >> 1);
    const int ckB = kh * 2 + (mm & 1);

    float acc[2][4][4];
    #pragma unroll
    for (int mt = 0; mt < 2; mt++)
        #pragma unroll
        for (int nt = 0; nt < 4; nt++)
            #pragma unroll
            for (int j = 0; j < 4; j++) acc[mt][nt][j] = 0.0f;

    #pragma unroll
    for (int it = 0; it < NITER; ++it) {
        CP_WAIT2();
        __syncthreads();              // stage it (A STS + B cp.async) visible

        if (isA) {
            if (it + 2 < NITER) {
                if (it & 1) LDG_A(rr1, (it + 2) * BKT);
                else        LDG_A(rr0, (it + 2) * BKT);
            }
        } else {
            if (it + 3 < NITER) { CPB((it + 3) & (NSTG - 1), (it + 3) * BKT); }
            else                { CP_COMMIT(); }
        }

        const uint32_t As = sb + A_OFF + (it & (NSTG - 1)) * A_STAGE;
        const uint32_t Bs = sb + B_OFF + (it & (NSTG - 1)) * B_STAGE;

        uint32_t af[2][4], bq[2][4];
        LDSM_X4(af[0], As + SWZ(rowA0,      ckA));
        LDSM_X4(af[1], As + SWZ(rowA0 + 16, ckA));
        LDSM_X4(bq[0], Bs + SWZ(rowB0,      ckB));
        LDSM_X4(bq[1], Bs + SWZ(rowB0 + 16, ckB));
        #pragma unroll
        for (int mt = 0; mt < 2; mt++) {
            MMA_BF16(acc[mt][0], af[mt], bq[0][0], bq[0][1]);
            MMA_BF16(acc[mt][1], af[mt], bq[0][2], bq[0][3]);
            MMA_BF16(acc[mt][2], af[mt], bq[1][0], bq[1][1]);
            MMA_BF16(acc[mt][3], af[mt], bq[1][2], bq[1][3]);
        }

        if (isA && it + 1 < NITER) {
            if (it & 1) PROD((it + 1) & (NSTG - 1), rr0, (it + 1) * BKT);
            else        PROD((it + 1) & (NSTG - 1), rr1, (it + 1) * BKT);
        }
    }

    // ---- publish e2 partials; wait for all stage reads to finish ----
    if (isA) ((float*)(smem + E2_OFF))[aq * 64 + arow] = e2p;
    __syncthreads();

    // ---- k-pair reduction through SMEM (reuse stage area) ----
    float* red = (float*)(smem + A_OFF + (wid & 7) * 4096);
    if (kh) {
        #pragma unroll
        for (int mt = 0; mt < 2; mt++)
            #pragma unroll
            for (int nt = 0; nt < 4; nt++)
                #pragma unroll
                for (int j = 0; j < 4; j++)
                    red[((mt * 4 + nt) * 4 + j) * 32 + lane] = acc[mt][nt][j];
    }
    __syncthreads();

    if (!kh) {
        const float* sE2 = (const float*)(smem + E2_OFF);
        const float* moff = (const float*)(smem + MOFF_OFF);
        #pragma unroll
        for (int mt = 0; mt < 2; mt++) {
            const int r0 = wm * 32 + mt * 16 + g;
            const float rb0 = -0.5f * (sE2[r0] + sE2[64 + r0] + sE2[128 + r0] + sE2[192 + r0]);
            const float rb1 = -0.5f * (sE2[r0 + 8] + sE2[64 + r0 + 8] + sE2[128 + r0 + 8] + sE2[192 + r0 + 8]);
            float* orow0 = out + (size_t)(m0 + r0) * GS_L;
            float* orow1 = orow0 + 8 * GS_L;
            #pragma unroll
            for (int nt = 0; nt < 4; nt++) {
                const int base = (mt * 4 + nt) * 4;
                const int col = wn * 32 + nt * 8 + tig * 2;
                float2 mo = *(const float2*)(moff + col);
                float2 o0, o1;
                o0.x = acc[mt][nt][0] + red[(base + 0) * 32 + lane] + rb0 + mo.x;
                o0.y = acc[mt][nt][1] + red[(base + 1) * 32 + lane] + rb0 + mo.y;
                o1.x = acc[mt][nt][2] + red[(base + 2) * 32 + lane] + rb1 + mo.x;
                o1.y = acc[mt][nt][3] + red[(base + 3) * 32 + lane] + rb1 + mo.y;
                *(float2*)(orow0 + col) = o0;
                *(float2*)(orow1 + col) = o1;
            }
        }
    }
}

extern "C" void kernel_launch(void* const* d_in, const int* in_sizes, int n_in,
                              void* d_out, int out_size) {
    const float* emb   = (const float*)d_in[0];   // [8, 2048, 512] f32
    const float* means = (const float*)d_in[1];   // [128, 512] f32
    const float* var   = (const float*)d_in[2];   // [512] f32
    float* out = (float*)d_out;                   // [8, 2048, 128] f32
    (void)in_sizes; (void)n_in; (void)out_size;

    cudaFuncSetAttribute(gs_main, cudaFuncAttributeMaxDynamicSharedMemorySize, SMEM_TOTAL);
    gs_prep<<<GS_L, 128>>>(means, var);
    gs_main<<<GS_M / BM, NTHREADS, SMEM_TOTAL>>>(emb, var, out);
}